// round 14
// baseline (speedup 1.0000x reference)
#include <cuda_runtime.h>
#include <math.h>
#include <stdint.h>

#define BATCH 128
#define SEQ   128
#define DIM   100
#define QNB   4
#define SNB   4
#define KCN   4
#define RKN   10
#define TSTEPS 127
#define NEGV  -1000000000.0f

// ---------------- device scratch (no allocations) ----------------
__device__ float g_Qemb[BATCH*SEQ*DIM];
__device__ float g_G[(size_t)BATCH*SEQ*SEQ];
__device__ int   g_top[TSTEPS*BATCH*RKN];
__device__ float g_qc[(size_t)TSTEPS*BATCH*5*DIM];
__device__ float g_qtw[TSTEPS*BATCH*5];
__device__ float g_EMB[(size_t)TSTEPS*BATCH*DIM];
__device__ float g_GI1[(size_t)TSTEPS*BATCH*300];
__device__ float g_gier[2*300];
__device__ float g_H1N[(size_t)TSTEPS*BATCH*DIM];
__device__ float g_G2ALL[(size_t)TSTEPS*BATCH*DIM];
__device__ float g_KTW[TSTEPS*BATCH];
__device__ float g_kz;
__device__ int   g_cm_mode;
__device__ int   g_SYNC[64];

#define BAR1() asm volatile("bar.sync 1, 128;" ::: "memory")
#define BAR2() asm volatile("bar.sync 2, 128;" ::: "memory")

// ---------------- helpers ----------------
__device__ __forceinline__ float sigm(float x){ return 1.f/(1.f+expf(-x)); }

__device__ __forceinline__ float wredsum(float v){
#pragma unroll
    for (int o = 16; o; o >>= 1) v += __shfl_xor_sync(0xFFFFFFFFu, v, o);
    return v;
}

template<int N4>
__device__ __forceinline__ float dotw(const float* __restrict__ w, const float* x){
    const float4* w4 = reinterpret_cast<const float4*>(w);
    float acc = 0.f;
#pragma unroll
    for (int i = 0; i < N4; i++){
        float4 wv = __ldg(w4+i);
        acc = fmaf(wv.x, x[4*i+0], acc);
        acc = fmaf(wv.y, x[4*i+1], acc);
        acc = fmaf(wv.z, x[4*i+2], acc);
        acc = fmaf(wv.w, x[4*i+3], acc);
    }
    return acc;
}

// 4-vector dot, weight in SMEM
__device__ __forceinline__ void dot4s(const float* w,
        const float* x0, const float* x1, const float* x2, const float* x3,
        float& a0, float& a1, float& a2, float& a3){
    const float4* w4 = (const float4*)w;
    const float4* p0 = (const float4*)x0;
    const float4* p1 = (const float4*)x1;
    const float4* p2 = (const float4*)x2;
    const float4* p3 = (const float4*)x3;
#pragma unroll
    for (int i = 0; i < 25; i++){
        float4 wv = w4[i];
        float4 u0 = p0[i], u1 = p1[i], u2 = p2[i], u3 = p3[i];
        a0 = fmaf(wv.x,u0.x,a0); a0 = fmaf(wv.y,u0.y,a0); a0 = fmaf(wv.z,u0.z,a0); a0 = fmaf(wv.w,u0.w,a0);
        a1 = fmaf(wv.x,u1.x,a1); a1 = fmaf(wv.y,u1.y,a1); a1 = fmaf(wv.z,u1.z,a1); a1 = fmaf(wv.w,u1.w,a1);
        a2 = fmaf(wv.x,u2.x,a2); a2 = fmaf(wv.y,u2.y,a2); a2 = fmaf(wv.z,u2.z,a2); a2 = fmaf(wv.w,u2.w,a2);
        a3 = fmaf(wv.x,u3.x,a3); a3 = fmaf(wv.y,u3.y,a3); a3 = fmaf(wv.z,u3.z,a3); a3 = fmaf(wv.w,u3.w,a3);
    }
}

// 4-vector dot, weight in GMEM
__device__ __forceinline__ void dot4(const float* __restrict__ w,
        const float* x0, const float* x1, const float* x2, const float* x3,
        float& a0, float& a1, float& a2, float& a3){
    const float4* w4 = (const float4*)w;
    const float4* p0 = (const float4*)x0;
    const float4* p1 = (const float4*)x1;
    const float4* p2 = (const float4*)x2;
    const float4* p3 = (const float4*)x3;
#pragma unroll
    for (int i = 0; i < 25; i++){
        float4 wv = __ldg(w4+i);
        float4 u0 = p0[i], u1 = p1[i], u2 = p2[i], u3 = p3[i];
        a0 = fmaf(wv.x,u0.x,a0); a0 = fmaf(wv.y,u0.y,a0); a0 = fmaf(wv.z,u0.z,a0); a0 = fmaf(wv.w,u0.w,a0);
        a1 = fmaf(wv.x,u1.x,a1); a1 = fmaf(wv.y,u1.y,a1); a1 = fmaf(wv.z,u1.z,a1); a1 = fmaf(wv.w,u1.w,a1);
        a2 = fmaf(wv.x,u2.x,a2); a2 = fmaf(wv.y,u2.y,a2); a2 = fmaf(wv.z,u2.z,a2); a2 = fmaf(wv.w,u2.w,a2);
        a3 = fmaf(wv.x,u3.x,a3); a3 = fmaf(wv.y,u3.y,a3); a3 = fmaf(wv.z,u3.z,a3); a3 = fmaf(wv.w,u3.w,a3);
    }
}

#define FMA4A(acc,Wv,Xv) { acc = fmaf(Wv.x,Xv.x,acc); acc = fmaf(Wv.y,Xv.y,acc); \
                           acc = fmaf(Wv.z,Xv.z,acc); acc = fmaf(Wv.w,Xv.w,acc); }

// ---------------- fused setup ----------------
__global__ void __launch_bounds__(256) k_pre(
    const float* __restrict__ Eq, const int* __restrict__ question,
    const unsigned char* __restrict__ cm,
    const float* __restrict__ bquery, const float* __restrict__ WW,
    const float* __restrict__ Wih1, const float* __restrict__ bih1,
    const float* __restrict__ Er, float* __restrict__ out)
{
    int gtid = blockIdx.x*256 + threadIdx.x;
    if (gtid < BATCH*SEQ) out[gtid] = 0.f;
    if (gtid < 64) g_SYNC[gtid] = 0;
    if (gtid >= 16384 && gtid < 16416){
        int lane = gtid - 16384;
        int intOK = 1, fltOK = 1;
        for (int g = lane; g < 1000; g += 32){
            uint32_t v = 0;
            v |= (uint32_t)cm[4*g+0];
            v |= (uint32_t)cm[4*g+1] << 8;
            v |= (uint32_t)cm[4*g+2] << 16;
            v |= (uint32_t)cm[4*g+3] << 24;
            if (!(v == 0u || v == 1u)) intOK = 0;
            if (!(v == 0u || v == 0x3F800000u)) fltOK = 0;
        }
        intOK = __all_sync(0xFFFFFFFFu, intOK);
        fltOK = __all_sync(0xFFFFFFFFu, fltOK);
        if (lane == 0) g_cm_mode = intOK ? 1 : (fltOK ? 2 : 0);
    }
    if (gtid >= 16416 && gtid < 16448){
        int lane = gtid - 16416;
        float v = 0.f;
        for (int d = lane; d < DIM; d += 32) v += tanhf(__ldg(&bquery[d])) * __ldg(&WW[DIM+d]);
        v = wredsum(v);
        if (lane == 0) g_kz = v;
    }
    if (gtid >= 16448 && gtid < 17048){
        int idx = gtid - 16448;
        int r = idx / 300, o = idx - r*300;
        g_gier[idx] = dotw<25>(Wih1 + o*2*DIM + DIM, Er + r*DIM) + __ldg(&bih1[o]);
    }
    int n = BATCH*SEQ*DIM;
    for (int i = gtid; i < n; i += 2048*256){
        int bs = i / DIM, d = i - bs*DIM;
        g_Qemb[i] = __ldg(&Eq[(size_t)question[bs]*DIM + d]);
    }
}

// ---------------- Gram matrix ----------------
__global__ void __launch_bounds__(256) k_gmat(){
    int b = blockIdx.y;
    int i0 = blockIdx.x * 32;
    int tid = threadIdx.x;
    __shared__ __align__(16) float sQ[32*DIM];
    const float* Qb = g_Qemb + (size_t)b*SEQ*DIM;
    for (int i = tid; i < 32*DIM; i += 256){
        int r = i / DIM, d = i - r*DIM;
        sQ[i] = Qb[(size_t)(i0 + r)*DIM + d];
    }
    __syncthreads();
    int ti = (tid >> 5) * 4;
    int tj = (tid & 31) * 4;
    float acc[4][4];
#pragma unroll
    for (int a = 0; a < 4; a++)
#pragma unroll
        for (int c = 0; c < 4; c++) acc[a][c] = 0.f;
    const float4* qi0 = (const float4*)(sQ + (ti+0)*DIM);
    const float4* qi1 = (const float4*)(sQ + (ti+1)*DIM);
    const float4* qi2 = (const float4*)(sQ + (ti+2)*DIM);
    const float4* qi3 = (const float4*)(sQ + (ti+3)*DIM);
    const float4* qj0 = (const float4*)(Qb + (size_t)(tj+0)*DIM);
    const float4* qj1 = (const float4*)(Qb + (size_t)(tj+1)*DIM);
    const float4* qj2 = (const float4*)(Qb + (size_t)(tj+2)*DIM);
    const float4* qj3 = (const float4*)(Qb + (size_t)(tj+3)*DIM);
#pragma unroll
    for (int k = 0; k < 25; k++){
        float4 A0 = qi0[k], A1 = qi1[k], A2 = qi2[k], A3 = qi3[k];
        float4 B0 = __ldg(qj0+k), B1 = __ldg(qj1+k), B2 = __ldg(qj2+k), B3 = __ldg(qj3+k);
        FMA4A(acc[0][0],A0,B0) FMA4A(acc[0][1],A0,B1) FMA4A(acc[0][2],A0,B2) FMA4A(acc[0][3],A0,B3)
        FMA4A(acc[1][0],A1,B0) FMA4A(acc[1][1],A1,B1) FMA4A(acc[1][2],A1,B2) FMA4A(acc[1][3],A1,B3)
        FMA4A(acc[2][0],A2,B0) FMA4A(acc[2][1],A2,B1) FMA4A(acc[2][2],A2,B2) FMA4A(acc[2][3],A2,B3)
        FMA4A(acc[3][0],A3,B0) FMA4A(acc[3][1],A3,B1) FMA4A(acc[3][2],A3,B2) FMA4A(acc[3][3],A3,B3)
    }
    float* Gb = g_G + (size_t)b*SEQ*SEQ;
#pragma unroll
    for (int a = 0; a < 4; a++)
#pragma unroll
        for (int c = 0; c < 4; c++)
            Gb[(size_t)(i0+ti+a)*SEQ + (tj+c)] = acc[a][c];
}

// ---------------- top-10 ----------------
__global__ void k_topk(){
    int wg   = blockIdx.x*(blockDim.x >> 5) + (threadIdx.x >> 5);
    int lane = threadIdx.x & 31;
    if (wg >= 116*BATCH) return;
    int t = 11 + wg / BATCH;
    int b = wg % BATCH;
    const float* Gb = g_G + (size_t)b*SEQ*SEQ;
    unsigned selm = 0;
    for (int r = 0; r < RKN; r++){
        float bv = -INFINITY; int bi = SEQ;
#pragma unroll
        for (int m = 0; m < 4; m++){
            int s = lane + 32*m;
            if (s < t && !((selm >> m) & 1u)){
                float v = __ldg(&Gb[(size_t)s*SEQ + (t+1)]);
                if (v > bv || (v == bv && s < bi)){ bv = v; bi = s; }
            }
        }
#pragma unroll
        for (int o = 16; o; o >>= 1){
            float ov = __shfl_xor_sync(0xFFFFFFFFu, bv, o);
            int   oi = __shfl_xor_sync(0xFFFFFFFFu, bi, o);
            if (ov > bv || (ov == bv && oi < bi)){ bv = ov; bi = oi; }
        }
        if ((bi & 31) == lane) selm |= 1u << (bi >> 5);
        if (lane == 0) g_top[((size_t)t*BATCH + b)*RKN + r] = bi;
    }
}

// ---------------- merged aggregate + qc (R7 proven version) ----------------
__global__ void __launch_bounds__(256) k_aggqc(
    const float* __restrict__ Eq, const float* __restrict__ Ec,
    const int* __restrict__ question, const int* __restrict__ mask,
    const int* __restrict__ qnb, const int* __restrict__ snb,
    const float* __restrict__ Wagg, const float* __restrict__ bagg,
    const float* __restrict__ Wlast, const float* __restrict__ blast,
    const int* __restrict__ concept_idx, const void* __restrict__ cmask,
    const float* __restrict__ W_key, const float* __restrict__ b_key,
    const float* __restrict__ W_W)
{
    int tb = blockIdx.x;
    int t = tb >> 7, b = tb & 127;

    __shared__ __align__(16) float sE1[4*DIM], sE2[16*DIM], sU[16*DIM], sV[16*DIM];
    __shared__ __align__(16) float sV1[4*DIM], sT4[4*DIM], sW1[4*DIM];
    __shared__ __align__(16) float vA[DIM], vB[DIM], vC[DIM];
    __shared__ int sN1[4], sN2[16], sN3[64];
    __shared__ __align__(16) float sqc[5*DIM], sQt[5*DIM];

    if (threadIdx.x < 128){
        // ================= aggregation half =================
        int tid = threadIdx.x;
        int q_t = question[b*SEQ + t];
        float* dst = g_EMB + (size_t)tb*DIM;
        if (mask[b*SEQ + t] == 0){
            for (int d = tid; d < DIM; d += 128) dst[d] = __ldg(&Eq[(size_t)q_t*DIM + d]);
        } else {
            if (tid < QNB) sN1[tid] = __ldg(&qnb[q_t*QNB + tid]);
            BAR1();
            if (tid < 16) sN2[tid] = __ldg(&snb[sN1[tid >> 2]*SNB + (tid & 3)]);
            BAR1();
            if (tid < 64) sN3[tid] = __ldg(&qnb[sN2[tid >> 2]*QNB + (tid & 3)]);
            for (int i = tid; i < 4*DIM; i += 128){
                int r = i / DIM, d = i - r*DIM;
                sE1[i] = __ldg(&Ec[(size_t)sN1[r]*DIM + d]);
            }
            BAR1();
            for (int i = tid; i < 16*DIM; i += 128){
                int k = i / DIM, d = i - k*DIM;
                float e2v = __ldg(&Eq[(size_t)sN2[k]*DIM + d]);
                float s3 = __ldg(&Ec[(size_t)sN3[4*k+0]*DIM + d]) + __ldg(&Ec[(size_t)sN3[4*k+1]*DIM + d])
                         + __ldg(&Ec[(size_t)sN3[4*k+2]*DIM + d]) + __ldg(&Ec[(size_t)sN3[4*k+3]*DIM + d]);
                sE2[i] = e2v;
                sU[i]  = e2v + 0.25f*s3;
            }
            BAR1();
            // ---- stage i=0: sV[k][o] = tanh(Wagg2 @ sU[k] + b2), 4o x 4k register tiles ----
            for (int task = tid; task < 100; task += 128){
                int og = task % 25, kg = task / 25;
                int o0 = og*4, k0 = kg*4;
                float acc[4][4];
#pragma unroll
                for (int a = 0; a < 4; a++)
#pragma unroll
                    for (int c = 0; c < 4; c++) acc[a][c] = 0.f;
                const float4* w0 = (const float4*)(Wagg + 2*DIM*DIM + (o0+0)*DIM);
                const float4* w1 = (const float4*)(Wagg + 2*DIM*DIM + (o0+1)*DIM);
                const float4* w2 = (const float4*)(Wagg + 2*DIM*DIM + (o0+2)*DIM);
                const float4* w3 = (const float4*)(Wagg + 2*DIM*DIM + (o0+3)*DIM);
                const float4* x0 = (const float4*)(sU + (k0+0)*DIM);
                const float4* x1 = (const float4*)(sU + (k0+1)*DIM);
                const float4* x2 = (const float4*)(sU + (k0+2)*DIM);
                const float4* x3 = (const float4*)(sU + (k0+3)*DIM);
#pragma unroll
                for (int i = 0; i < 25; i++){
                    float4 W0 = __ldg(w0+i), W1 = __ldg(w1+i), W2 = __ldg(w2+i), W3 = __ldg(w3+i);
                    float4 X0 = x0[i], X1 = x1[i], X2 = x2[i], X3 = x3[i];
                    FMA4A(acc[0][0],W0,X0) FMA4A(acc[0][1],W0,X1) FMA4A(acc[0][2],W0,X2) FMA4A(acc[0][3],W0,X3)
                    FMA4A(acc[1][0],W1,X0) FMA4A(acc[1][1],W1,X1) FMA4A(acc[1][2],W1,X2) FMA4A(acc[1][3],W1,X3)
                    FMA4A(acc[2][0],W2,X0) FMA4A(acc[2][1],W2,X1) FMA4A(acc[2][2],W2,X2) FMA4A(acc[2][3],W2,X3)
                    FMA4A(acc[3][0],W3,X0) FMA4A(acc[3][1],W3,X1) FMA4A(acc[3][2],W3,X2) FMA4A(acc[3][3],W3,X3)
                }
#pragma unroll
                for (int a = 0; a < 4; a++){
                    float bb = __ldg(&bagg[2*DIM + o0 + a]);
#pragma unroll
                    for (int c = 0; c < 4; c++)
                        sV[(k0+c)*DIM + (o0+a)] = tanhf(acc[a][c] + bb);
                }
            }
            for (int i = tid; i < 4*DIM; i += 128){
                int r = i / DIM, d = i - r*DIM;
                sT4[i] = sE1[i] + 0.25f*(sE2[(4*r+0)*DIM+d] + sE2[(4*r+1)*DIM+d]
                                       + sE2[(4*r+2)*DIM+d] + sE2[(4*r+3)*DIM+d]);
            }
            for (int d = tid; d < DIM; d += 128)
                vA[d] = __ldg(&Eq[(size_t)q_t*DIM + d]) + 0.25f*(sE1[d] + sE1[DIM+d] + sE1[2*DIM+d] + sE1[3*DIM+d]);
            BAR1();
            // ---- sV1 = tanh(Wagg1 @ sT4) (2o x 4r), vB = tanh(Wagg0 @ vA) (2o) ----
            for (int task = tid; task < 100; task += 128){
                if (task < 50){
                    int o0 = task*2;
                    float acc[2][4];
#pragma unroll
                    for (int a = 0; a < 2; a++)
#pragma unroll
                        for (int c = 0; c < 4; c++) acc[a][c] = 0.f;
                    const float4* w0 = (const float4*)(Wagg + DIM*DIM + (o0+0)*DIM);
                    const float4* w1 = (const float4*)(Wagg + DIM*DIM + (o0+1)*DIM);
                    const float4* x0 = (const float4*)(sT4 + 0*DIM);
                    const float4* x1 = (const float4*)(sT4 + 1*DIM);
                    const float4* x2 = (const float4*)(sT4 + 2*DIM);
                    const float4* x3 = (const float4*)(sT4 + 3*DIM);
#pragma unroll
                    for (int i = 0; i < 25; i++){
                        float4 W0 = __ldg(w0+i), W1 = __ldg(w1+i);
                        float4 X0 = x0[i], X1 = x1[i], X2 = x2[i], X3 = x3[i];
                        FMA4A(acc[0][0],W0,X0) FMA4A(acc[0][1],W0,X1) FMA4A(acc[0][2],W0,X2) FMA4A(acc[0][3],W0,X3)
                        FMA4A(acc[1][0],W1,X0) FMA4A(acc[1][1],W1,X1) FMA4A(acc[1][2],W1,X2) FMA4A(acc[1][3],W1,X3)
                    }
#pragma unroll
                    for (int a = 0; a < 2; a++){
                        float bb = __ldg(&bagg[DIM + o0 + a]);
#pragma unroll
                        for (int c = 0; c < 4; c++)
                            sV1[c*DIM + (o0+a)] = tanhf(acc[a][c] + bb);
                    }
                } else {
                    int o0 = (task - 50)*2;
                    float a0 = dotw<25>(Wagg + (o0+0)*DIM, vA);
                    float a1 = dotw<25>(Wagg + (o0+1)*DIM, vA);
                    vB[o0+0] = tanhf(a0 + __ldg(&bagg[o0+0]));
                    vB[o0+1] = tanhf(a1 + __ldg(&bagg[o0+1]));
                }
            }
            BAR1();
            // ---- stage i=1 averaging ----
            for (int i = tid; i < 4*DIM; i += 128){
                int r = i / DIM, d = i - r*DIM;
                sT4[i] = sV1[i] + 0.25f*(sV[(4*r+0)*DIM+d] + sV[(4*r+1)*DIM+d]
                                       + sV[(4*r+2)*DIM+d] + sV[(4*r+3)*DIM+d]);
            }
            for (int d = tid; d < DIM; d += 128)
                vA[d] = vB[d] + 0.25f*(sV1[d] + sV1[DIM+d] + sV1[2*DIM+d] + sV1[3*DIM+d]);
            BAR1();
            // ---- sW1 = tanh(Wagg1 @ sT4) (2o x 4r), vC = tanh(Wagg0 @ vA) (2o) ----
            for (int task = tid; task < 100; task += 128){
                if (task < 50){
                    int o0 = task*2;
                    float acc[2][4];
#pragma unroll
                    for (int a = 0; a < 2; a++)
#pragma unroll
                        for (int c = 0; c < 4; c++) acc[a][c] = 0.f;
                    const float4* w0 = (const float4*)(Wagg + DIM*DIM + (o0+0)*DIM);
                    const float4* w1 = (const float4*)(Wagg + DIM*DIM + (o0+1)*DIM);
                    const float4* x0 = (const float4*)(sT4 + 0*DIM);
                    const float4* x1 = (const float4*)(sT4 + 1*DIM);
                    const float4* x2 = (const float4*)(sT4 + 2*DIM);
                    const float4* x3 = (const float4*)(sT4 + 3*DIM);
#pragma unroll
                    for (int i = 0; i < 25; i++){
                        float4 W0 = __ldg(w0+i), W1 = __ldg(w1+i);
                        float4 X0 = x0[i], X1 = x1[i], X2 = x2[i], X3 = x3[i];
                        FMA4A(acc[0][0],W0,X0) FMA4A(acc[0][1],W0,X1) FMA4A(acc[0][2],W0,X2) FMA4A(acc[0][3],W0,X3)
                        FMA4A(acc[1][0],W1,X0) FMA4A(acc[1][1],W1,X1) FMA4A(acc[1][2],W1,X2) FMA4A(acc[1][3],W1,X3)
                    }
#pragma unroll
                    for (int a = 0; a < 2; a++){
                        float bb = __ldg(&bagg[DIM + o0 + a]);
#pragma unroll
                        for (int c = 0; c < 4; c++)
                            sW1[c*DIM + (o0+a)] = tanhf(acc[a][c] + bb);
                    }
                } else {
                    int o0 = (task - 50)*2;
                    float a0 = dotw<25>(Wagg + (o0+0)*DIM, vA);
                    float a1 = dotw<25>(Wagg + (o0+1)*DIM, vA);
                    vC[o0+0] = tanhf(a0 + __ldg(&bagg[o0+0]));
                    vC[o0+1] = tanhf(a1 + __ldg(&bagg[o0+1]));
                }
            }
            BAR1();
            // ---- stage i=2 ----
            for (int d = tid; d < DIM; d += 128)
                vA[d] = vC[d] + 0.25f*(sW1[d] + sW1[DIM+d] + sW1[2*DIM+d] + sW1[3*DIM+d]);
            BAR1();
            for (int task = tid; task < 50; task += 128){
                int o0 = task*2;
                float a0 = dotw<25>(Wagg + (o0+0)*DIM, vA);
                float a1 = dotw<25>(Wagg + (o0+1)*DIM, vA);
                vB[o0+0] = tanhf(a0 + __ldg(&bagg[o0+0]));
                vB[o0+1] = tanhf(a1 + __ldg(&bagg[o0+1]));
            }
            BAR1();
            for (int task = tid; task < 50; task += 128){
                int o0 = task*2;
                float a0 = dotw<25>(Wlast + (o0+0)*DIM, vB);
                float a1 = dotw<25>(Wlast + (o0+1)*DIM, vB);
                dst[o0+0] = tanhf(a0 + __ldg(&blast[o0+0]));
                dst[o0+1] = tanhf(a1 + __ldg(&blast[o0+1]));
            }
        }
    } else {
        // ================= qc half =================
        int tid = threadIdx.x - 128;
        int qn = question[b*SEQ + t + 1];
        int mode = g_cm_mode;
        for (int i = tid; i < 5*DIM; i += 128){
            int q = i / DIM, d = i - q*DIM;
            float v;
            if (q == 0){
                v = g_Qemb[((size_t)b*SEQ + t + 1)*DIM + d];
            } else {
                int fi = qn*KCN + (q - 1);
                bool mk;
                if (mode == 1)      mk = ((const int*)cmask)[fi] != 0;
                else if (mode == 2) mk = ((const float*)cmask)[fi] != 0.f;
                else                mk = ((const unsigned char*)cmask)[fi] != 0;
                int ci = __ldg(&concept_idx[fi]);
                v = mk ? __ldg(&Ec[(size_t)ci*DIM + d]) : 0.f;
            }
            sqc[i] = v;
            g_qc[((size_t)tb)*(5*DIM) + i] = v;
        }
        BAR2();
        for (int task = tid; task < 50; task += 128){
            int o0 = task*2;
            float acc[2][5];
#pragma unroll
            for (int a = 0; a < 2; a++)
#pragma unroll
                for (int c = 0; c < 5; c++) acc[a][c] = 0.f;
            const float4* w0 = (const float4*)(W_key + (o0+0)*DIM);
            const float4* w1 = (const float4*)(W_key + (o0+1)*DIM);
            const float4* x0 = (const float4*)(sqc + 0*DIM);
            const float4* x1 = (const float4*)(sqc + 1*DIM);
            const float4* x2 = (const float4*)(sqc + 2*DIM);
            const float4* x3 = (const float4*)(sqc + 3*DIM);
            const float4* x4 = (const float4*)(sqc + 4*DIM);
#pragma unroll
            for (int i = 0; i < 25; i++){
                float4 W0 = __ldg(w0+i), W1 = __ldg(w1+i);
                float4 X0 = x0[i], X1 = x1[i], X2 = x2[i], X3 = x3[i], X4 = x4[i];
                FMA4A(acc[0][0],W0,X0) FMA4A(acc[0][1],W0,X1) FMA4A(acc[0][2],W0,X2) FMA4A(acc[0][3],W0,X3) FMA4A(acc[0][4],W0,X4)
                FMA4A(acc[1][0],W1,X0) FMA4A(acc[1][1],W1,X1) FMA4A(acc[1][2],W1,X2) FMA4A(acc[1][3],W1,X3) FMA4A(acc[1][4],W1,X4)
            }
#pragma unroll
            for (int a = 0; a < 2; a++){
                float bb = __ldg(&b_key[o0+a]);
#pragma unroll
                for (int c = 0; c < 5; c++)
                    sQt[c*DIM + (o0+a)] = tanhf(acc[a][c] + bb);
            }
        }
        BAR2();
        int w = tid >> 5, lane = tid & 31;
        for (int q = w; q < 5; q += 4){
            float part = 0.f;
            for (int d = lane; d < DIM; d += 32) part += sQt[q*DIM + d] * __ldg(&W_W[d]);
            part = wredsum(part);
            if (lane == 0) g_qtw[((size_t)tb)*5 + q] = part;
        }
    }
}

// ---------------- gi1 ----------------
__global__ void __launch_bounds__(256) k_gi1(const float* __restrict__ Wih1,
                                             const int* __restrict__ response){
    int t = blockIdx.x, zb = blockIdx.y;
    int tid = threadIdx.x;
    __shared__ __align__(16) float sE[DIM*64];
    __shared__ int sRt[64];
    for (int i = tid; i < 64*DIM; i += 256){
        int bb = i / DIM, d = i - bb*DIM;
        sE[d*64 + bb] = g_EMB[((size_t)t*BATCH + zb*64 + bb)*DIM + d];
    }
    if (tid < 64) sRt[tid] = response[(zb*64 + tid)*SEQ + t];
    __syncthreads();
    for (int tt = tid; tt < 600; tt += 256){
        int ro = (tt >> 3) * 4;
        int bo = (tt & 7) * 8;
        float acc[4][8];
#pragma unroll
        for (int i = 0; i < 4; i++)
#pragma unroll
            for (int j = 0; j < 8; j++) acc[i][j] = 0.f;
        for (int k = 0; k < DIM; k++){
            float w0 = __ldg(&Wih1[(size_t)(ro+0)*2*DIM + k]);
            float w1 = __ldg(&Wih1[(size_t)(ro+1)*2*DIM + k]);
            float w2 = __ldg(&Wih1[(size_t)(ro+2)*2*DIM + k]);
            float w3 = __ldg(&Wih1[(size_t)(ro+3)*2*DIM + k]);
            const float* e = sE + k*64 + bo;
#pragma unroll
            for (int j = 0; j < 8; j++){
                float ev = e[j];
                acc[0][j] = fmaf(w0, ev, acc[0][j]);
                acc[1][j] = fmaf(w1, ev, acc[1][j]);
                acc[2][j] = fmaf(w2, ev, acc[2][j]);
                acc[3][j] = fmaf(w3, ev, acc[3][j]);
            }
        }
#pragma unroll
        for (int i = 0; i < 4; i++)
#pragma unroll
            for (int j = 0; j < 8; j++){
                int b = zb*64 + bo + j;
                int o = ro + i;
                g_GI1[((size_t)t*BATCH + b)*300 + o] = acc[i][j] + g_gier[sRt[bo+j]*300 + o];
            }
    }
}

// ---------------- pipelined scan: 4 batch rows per pair (32 producer + 32 consumer CTAs) ----------------
__global__ void __launch_bounds__(320) k_scan2(
    const float* __restrict__ Whh1, const float* __restrict__ bhh1,
    const float* __restrict__ Wih2, const float* __restrict__ bih2,
    const float* __restrict__ Whh2, const float* __restrict__ bhh2,
    const float* __restrict__ h1i, const float* __restrict__ h2i)
{
    extern __shared__ __align__(16) float sW[];
    __shared__ __align__(16) float sH[4][DIM], sX[4][DIM];
    __shared__ __align__(16) float sGa[4][300], sGb[4][300];
    __shared__ float sba[300], sbb[300];

    int tid = threadIdx.x;
    int role = blockIdx.x >> 5;
    int pair = blockIdx.x & 31;
    int b0 = pair*4;

    if (role == 0){
        for (int i = tid; i < 30000; i += 320) sW[i] = Whh1[i];
        for (int i = tid; i < 300; i += 320) sba[i] = bhh1[i];
        for (int i = tid; i < 4*DIM; i += 320){
            int r = i / DIM, d = i - r*DIM;
            sH[r][d] = h1i[(b0+r)*DIM + d];
        }
        __syncthreads();
        for (int t = 0; t < TSTEPS; t++){
            if (tid < 300){
                float a0 = sba[tid], a1 = a0, a2 = a0, a3 = a0;
                dot4s(sW + tid*DIM, sH[0], sH[1], sH[2], sH[3], a0, a1, a2, a3);
                sGa[0][tid] = a0; sGa[1][tid] = a1; sGa[2][tid] = a2; sGa[3][tid] = a3;
            }
            for (int i = tid; i < 1200; i += 320){
                int r = i / 300, o = i - r*300;
                sGb[r][o] = g_GI1[((size_t)t*BATCH + b0 + r)*300 + o];
            }
            __syncthreads();
            for (int i = tid; i < 400; i += 320){
                int r = i / 100, d = i - r*100;
                float rr = sigm(sGb[r][d]       + sGa[r][d]);
                float zz = sigm(sGb[r][DIM+d]   + sGa[r][DIM+d]);
                float nn = tanhf(sGb[r][2*DIM+d] + rr*sGa[r][2*DIM+d]);
                float h1n = (1.f - zz)*nn + zz*sH[r][d];
                sH[r][d] = h1n;
                g_H1N[((size_t)t*BATCH + b0 + r)*DIM + d] = h1n;
            }
            __syncthreads();
            if (tid == 0){
                __threadfence();
                atomicExch(&g_SYNC[pair], t + 1);
            }
        }
    } else {
        for (int i = tid; i < 30000; i += 320) sW[i] = Wih2[i];
        for (int i = tid; i < 300; i += 320){ sba[i] = bhh2[i]; sbb[i] = bih2[i]; }
        for (int i = tid; i < 4*DIM; i += 320){
            int r = i / DIM, d = i - r*DIM;
            sH[r][d] = h2i[(b0+r)*DIM + d];
        }
        __syncthreads();
        for (int t = 0; t < TSTEPS; t++){
            // gh2 = Whh2@h2 (L1-resident global weights) — independent of h1n
            if (tid < 300){
                float a0 = sba[tid], a1 = a0, a2 = a0, a3 = a0;
                dot4(Whh2 + tid*DIM, sH[0], sH[1], sH[2], sH[3], a0, a1, a2, a3);
                sGa[0][tid] = a0; sGa[1][tid] = a1; sGa[2][tid] = a2; sGa[3][tid] = a3;
            }
            if (tid == 0){
                while (atomicAdd(&g_SYNC[pair], 0) < t + 1) __nanosleep(60);
                __threadfence();
            }
            __syncthreads();
            for (int i = tid; i < 400; i += 320){
                int r = i / 100, d = i - r*100;
                sX[r][d] = g_H1N[((size_t)t*BATCH + b0 + r)*DIM + d];
            }
            __syncthreads();
            if (tid < 300){
                float a0 = sbb[tid], a1 = a0, a2 = a0, a3 = a0;
                dot4s(sW + tid*DIM, sX[0], sX[1], sX[2], sX[3], a0, a1, a2, a3);
                sGb[0][tid] = a0; sGb[1][tid] = a1; sGb[2][tid] = a2; sGb[3][tid] = a3;
            }
            __syncthreads();
            for (int i = tid; i < 400; i += 320){
                int r = i / 100, d = i - r*100;
                float rr = sigm(sGb[r][d]       + sGa[r][d]);
                float zz = sigm(sGb[r][DIM+d]   + sGa[r][DIM+d]);
                float nn = tanhf(sGb[r][2*DIM+d] + rr*sGa[r][2*DIM+d]);
                float g2 = (1.f - zz)*nn + zz*sH[r][d];
                g_G2ALL[((size_t)t*BATCH + b0 + r)*DIM + d] = g2;
                if (t > 0) sH[r][d] = g2;
            }
            __syncthreads();
        }
    }
}

// ---------------- ktw, 4 per block ----------------
__global__ void __launch_bounds__(128) k_ktw(const float* __restrict__ Wquery,
                                             const float* __restrict__ bquery,
                                             const float* __restrict__ WW){
    int tb0 = blockIdx.x*4;
    int tid = threadIdx.x;
    __shared__ __align__(16) float sg2[4][DIM];
    __shared__ float sred[4][DIM];
    for (int i = tid; i < 4*DIM; i += 128){
        int j = i / DIM, d = i - j*DIM;
        sg2[j][d] = g_G2ALL[(size_t)(tb0 + j)*DIM + d];
    }
    __syncthreads();
    for (int o = tid; o < DIM; o += 128){
        float a0=0.f,a1=0.f,a2=0.f,a3=0.f;
        dot4(Wquery + o*DIM, sg2[0], sg2[1], sg2[2], sg2[3], a0,a1,a2,a3);
        float bq = __ldg(&bquery[o]);
        float wk = __ldg(&WW[DIM+o]);
        sred[0][o] = tanhf(a0+bq)*wk;
        sred[1][o] = tanhf(a1+bq)*wk;
        sred[2][o] = tanhf(a2+bq)*wk;
        sred[3][o] = tanhf(a3+bq)*wk;
    }
    __syncthreads();
    int w = tid >> 5, lane = tid & 31;
    float v = sred[w][lane] + sred[w][lane+32] + sred[w][lane+64]
            + (lane < 4 ? sred[w][lane+96] : 0.f);
    v = wredsum(v);
    if (lane == 0) g_KTW[tb0 + w] = v;
}

// ---------------- predict ----------------
__global__ void __launch_bounds__(128) k_predict(const float* __restrict__ bW,
                                                 float* __restrict__ out){
    int tb = blockIdx.x;
    int t = tb >> 7, b = tb & 127;
    int tid = threadIdx.x;
    __shared__ __align__(16) float sSt[11*DIM];
    __shared__ float sOg[55], sKtw[11], sQtw[5], sP[5];
    __shared__ int sSrc[11];

    if (tid < 11){
        int src = 0;
        float k;
        if (tid == 0){
            k = g_KTW[tb];
        } else {
            src = (t > RKN) ? g_top[((size_t)t*BATCH + b)*RKN + (tid-1)] : (tid-1);
            k = (src == 0) ? g_kz : g_KTW[(size_t)src*BATCH + b];
        }
        sSrc[tid] = src;
        sKtw[tid] = k;
    }
    if (tid >= 11 && tid < 16) sQtw[tid-11] = g_qtw[(size_t)tb*5 + (tid-11)];
    __syncthreads();
    for (int i = tid; i < 11*DIM; i += 128){
        int s = i / DIM, d = i - s*DIM;
        float v;
        if (s == 0) v = g_G2ALL[(size_t)tb*DIM + d];
        else {
            int src = sSrc[s];
            v = (src == 0) ? 0.f : g_G2ALL[((size_t)src*BATCH + b)*DIM + d];
        }
        sSt[i] = v;
    }
    __syncthreads();
    if (tid < 55){
        int q = tid / 11, s = tid - q*11;
        const float4* a = (const float4*)(g_qc + (size_t)tb*(5*DIM) + q*DIM);
        const float4* xx = (const float4*)(sSt + s*DIM);
        float acc = 0.f;
#pragma unroll
        for (int i = 0; i < 25; i++){
            float4 w = __ldg(a+i), u = xx[i];
            acc = fmaf(w.x,u.x,acc); acc = fmaf(w.y,u.y,acc);
            acc = fmaf(w.z,u.z,acc); acc = fmaf(w.w,u.w,acc);
        }
        sOg[tid] = acc;
    }
    __syncthreads();
    if (tid < 5){
        int q = tid;
        float bw0 = __ldg(&bW[0]);
        float qt = sQtw[q];
        float tmp[11]; float mx = -INFINITY;
#pragma unroll
        for (int s = 0; s < 11; s++){
            bool valid = (s == 0) || (t > RKN) || ((s-1) < t);
            float v = valid ? (qt + sKtw[s] + bw0) : NEGV;
            tmp[s] = v; mx = fmaxf(mx, v);
        }
        float se = 0.f, acc = 0.f;
#pragma unroll
        for (int s = 0; s < 11; s++){
            float e = expf(tmp[s] - mx);
            se += e; acc += e * sOg[q*11 + s];
        }
        sP[q] = acc / se;
    }
    __syncthreads();
    if (tid == 0){
        float p = sP[0] + sP[1] + sP[2] + sP[3] + sP[4];
        int col = (t == 0) ? 0 : (t + 1);
        out[b*SEQ + col] = p;
    }
}

// ---------------- launch ----------------
extern "C" void kernel_launch(void* const* d_in, const int* in_sizes, int n_in,
                              void* d_out, int out_size){
    const float* Eq     = (const float*)d_in[0];
    const float* Ec     = (const float*)d_in[1];
    const float* Er     = (const float*)d_in[2];
    const float* Wih1   = (const float*)d_in[3];
    const float* Whh1   = (const float*)d_in[4];
    const float* bih1   = (const float*)d_in[5];
    const float* bhh1   = (const float*)d_in[6];
    const float* Wih2   = (const float*)d_in[7];
    const float* Whh2   = (const float*)d_in[8];
    const float* bih2   = (const float*)d_in[9];
    const float* bhh2   = (const float*)d_in[10];
    const float* Wagg   = (const float*)d_in[11];
    const float* bagg   = (const float*)d_in[12];
    const float* Wlast  = (const float*)d_in[13];
    const float* blast  = (const float*)d_in[14];
    const float* Wquery = (const float*)d_in[15];
    const float* bquery = (const float*)d_in[16];
    const float* Wkey   = (const float*)d_in[17];
    const float* bkey   = (const float*)d_in[18];
    const float* WW     = (const float*)d_in[19];
    const float* bW     = (const float*)d_in[20];
    const float* h1i    = (const float*)d_in[21];
    const float* h2i    = (const float*)d_in[22];
    const int* question = (const int*)d_in[23];
    const int* response = (const int*)d_in[24];
    const int* maskp    = (const int*)d_in[25];
    const int* qnb      = (const int*)d_in[26];
    const int* snb      = (const int*)d_in[27];
    const int* cidx     = (const int*)d_in[28];
    const void* cmask   = d_in[29];
    float* out = (float*)d_out;

    cudaFuncSetAttribute(k_scan2, cudaFuncAttributeMaxDynamicSharedMemorySize, 122880);

    k_pre<<<2048, 256>>>(Eq, question, (const unsigned char*)cmask, bquery, WW,
                         Wih1, bih1, Er, out);
    k_gmat<<<dim3(4, BATCH), 256>>>();
    {
        int nwarp = 116*BATCH;
        int nb = (nwarp + 7) / 8;
        k_topk<<<nb, 256>>>();
    }
    k_aggqc<<<TSTEPS*BATCH, 256>>>(Eq, Ec, question, maskp, qnb, snb,
                                   Wagg, bagg, Wlast, blast,
                                   cidx, cmask, Wkey, bkey, WW);
    k_gi1<<<dim3(TSTEPS, 2), 256>>>(Wih1, response);
    k_scan2<<<64, 320, 120000>>>(Whh1, bhh1, Wih2, bih2, Whh2, bhh2, h1i, h2i);
    k_ktw<<<TSTEPS*BATCH/4, 128>>>(Wquery, bquery, WW);
    k_predict<<<TSTEPS*BATCH, 128>>>(bW, out);
}

// round 15
// speedup vs baseline: 1.9128x; 1.9128x over previous
#include <cuda_runtime.h>
#include <math.h>
#include <stdint.h>

#define BATCH 128
#define SEQ   128
#define DIM   100
#define QNB   4
#define SNB   4
#define KCN   4
#define RKN   10
#define TSTEPS 127
#define NEGV  -1000000000.0f

// ---------------- device scratch (no allocations) ----------------
__device__ float g_Qemb[BATCH*SEQ*DIM];
__device__ float g_G[(size_t)BATCH*SEQ*SEQ];
__device__ int   g_top[TSTEPS*BATCH*RKN];
__device__ float g_qc[(size_t)TSTEPS*BATCH*5*DIM];
__device__ float g_qtw[TSTEPS*BATCH*5];
__device__ float g_EMB[(size_t)TSTEPS*BATCH*DIM];
__device__ float g_GI1[(size_t)TSTEPS*BATCH*300];
__device__ float g_gier[2*300];
__device__ float g_H1N[(size_t)TSTEPS*BATCH*DIM];
__device__ float g_G2ALL[(size_t)TSTEPS*BATCH*DIM];
__device__ float g_KTW[TSTEPS*BATCH];
__device__ float g_kz;
__device__ int   g_cm_mode;
__device__ int   g_SYNC[64];

#define BAR1() asm volatile("bar.sync 1, 128;" ::: "memory")
#define BAR2() asm volatile("bar.sync 2, 128;" ::: "memory")

// ---------------- helpers ----------------
__device__ __forceinline__ float sigm(float x){ return 1.f/(1.f+expf(-x)); }

__device__ __forceinline__ float wredsum(float v){
#pragma unroll
    for (int o = 16; o; o >>= 1) v += __shfl_xor_sync(0xFFFFFFFFu, v, o);
    return v;
}

template<int N4>
__device__ __forceinline__ float dotw(const float* __restrict__ w, const float* x){
    const float4* w4 = reinterpret_cast<const float4*>(w);
    float acc = 0.f;
#pragma unroll
    for (int i = 0; i < N4; i++){
        float4 wv = __ldg(w4+i);
        acc = fmaf(wv.x, x[4*i+0], acc);
        acc = fmaf(wv.y, x[4*i+1], acc);
        acc = fmaf(wv.z, x[4*i+2], acc);
        acc = fmaf(wv.w, x[4*i+3], acc);
    }
    return acc;
}

__device__ __forceinline__ void dot2s(const float* w, const float* x0, const float* x1,
                                      float& a0, float& a1){
    const float4* w4 = (const float4*)w;
    const float4* p0 = (const float4*)x0;
    const float4* p1 = (const float4*)x1;
#pragma unroll
    for (int i = 0; i < 25; i++){
        float4 wv = w4[i];
        float4 u = p0[i], v = p1[i];
        a0 = fmaf(wv.x,u.x,a0); a0 = fmaf(wv.y,u.y,a0); a0 = fmaf(wv.z,u.z,a0); a0 = fmaf(wv.w,u.w,a0);
        a1 = fmaf(wv.x,v.x,a1); a1 = fmaf(wv.y,v.y,a1); a1 = fmaf(wv.z,v.z,a1); a1 = fmaf(wv.w,v.w,a1);
    }
}

__device__ __forceinline__ void dot2g(const float* __restrict__ w, const float* x0, const float* x1,
                                      float& a0, float& a1){
    const float4* w4 = (const float4*)w;
    const float4* p0 = (const float4*)x0;
    const float4* p1 = (const float4*)x1;
#pragma unroll
    for (int i = 0; i < 25; i++){
        float4 wv = __ldg(w4+i);
        float4 u = p0[i], v = p1[i];
        a0 = fmaf(wv.x,u.x,a0); a0 = fmaf(wv.y,u.y,a0); a0 = fmaf(wv.z,u.z,a0); a0 = fmaf(wv.w,u.w,a0);
        a1 = fmaf(wv.x,v.x,a1); a1 = fmaf(wv.y,v.y,a1); a1 = fmaf(wv.z,v.z,a1); a1 = fmaf(wv.w,v.w,a1);
    }
}

__device__ __forceinline__ void dot4(const float* __restrict__ w,
        const float* x0, const float* x1, const float* x2, const float* x3,
        float& a0, float& a1, float& a2, float& a3){
    const float4* w4 = (const float4*)w;
    const float4* p0 = (const float4*)x0;
    const float4* p1 = (const float4*)x1;
    const float4* p2 = (const float4*)x2;
    const float4* p3 = (const float4*)x3;
#pragma unroll
    for (int i = 0; i < 25; i++){
        float4 wv = __ldg(w4+i);
        float4 u0 = p0[i], u1 = p1[i], u2 = p2[i], u3 = p3[i];
        a0 = fmaf(wv.x,u0.x,a0); a0 = fmaf(wv.y,u0.y,a0); a0 = fmaf(wv.z,u0.z,a0); a0 = fmaf(wv.w,u0.w,a0);
        a1 = fmaf(wv.x,u1.x,a1); a1 = fmaf(wv.y,u1.y,a1); a1 = fmaf(wv.z,u1.z,a1); a1 = fmaf(wv.w,u1.w,a1);
        a2 = fmaf(wv.x,u2.x,a2); a2 = fmaf(wv.y,u2.y,a2); a2 = fmaf(wv.z,u2.z,a2); a2 = fmaf(wv.w,u2.w,a2);
        a3 = fmaf(wv.x,u3.x,a3); a3 = fmaf(wv.y,u3.y,a3); a3 = fmaf(wv.z,u3.z,a3); a3 = fmaf(wv.w,u3.w,a3);
    }
}

#define FMA4A(acc,Wv,Xv) { acc = fmaf(Wv.x,Xv.x,acc); acc = fmaf(Wv.y,Xv.y,acc); \
                           acc = fmaf(Wv.z,Xv.z,acc); acc = fmaf(Wv.w,Xv.w,acc); }

// ---------------- fused setup ----------------
__global__ void __launch_bounds__(256) k_pre(
    const float* __restrict__ Eq, const int* __restrict__ question,
    const unsigned char* __restrict__ cm,
    const float* __restrict__ bquery, const float* __restrict__ WW,
    const float* __restrict__ Wih1, const float* __restrict__ bih1,
    const float* __restrict__ Er, float* __restrict__ out)
{
    int gtid = blockIdx.x*256 + threadIdx.x;
    if (gtid < BATCH*SEQ) out[gtid] = 0.f;
    if (gtid < 64) g_SYNC[gtid] = 0;
    if (gtid >= 16384 && gtid < 16416){
        int lane = gtid - 16384;
        int intOK = 1, fltOK = 1;
        for (int g = lane; g < 1000; g += 32){
            uint32_t v = 0;
            v |= (uint32_t)cm[4*g+0];
            v |= (uint32_t)cm[4*g+1] << 8;
            v |= (uint32_t)cm[4*g+2] << 16;
            v |= (uint32_t)cm[4*g+3] << 24;
            if (!(v == 0u || v == 1u)) intOK = 0;
            if (!(v == 0u || v == 0x3F800000u)) fltOK = 0;
        }
        intOK = __all_sync(0xFFFFFFFFu, intOK);
        fltOK = __all_sync(0xFFFFFFFFu, fltOK);
        if (lane == 0) g_cm_mode = intOK ? 1 : (fltOK ? 2 : 0);
    }
    if (gtid >= 16416 && gtid < 16448){
        int lane = gtid - 16416;
        float v = 0.f;
        for (int d = lane; d < DIM; d += 32) v += tanhf(__ldg(&bquery[d])) * __ldg(&WW[DIM+d]);
        v = wredsum(v);
        if (lane == 0) g_kz = v;
    }
    if (gtid >= 16448 && gtid < 17048){
        int idx = gtid - 16448;
        int r = idx / 300, o = idx - r*300;
        g_gier[idx] = dotw<25>(Wih1 + o*2*DIM + DIM, Er + r*DIM) + __ldg(&bih1[o]);
    }
    int n = BATCH*SEQ*DIM;
    for (int i = gtid; i < n; i += 2048*256){
        int bs = i / DIM, d = i - bs*DIM;
        g_Qemb[i] = __ldg(&Eq[(size_t)question[bs]*DIM + d]);
    }
}

// ---------------- Gram matrix ----------------
__global__ void __launch_bounds__(256) k_gmat(){
    int b = blockIdx.y;
    int i0 = blockIdx.x * 32;
    int tid = threadIdx.x;
    __shared__ __align__(16) float sQ[32*DIM];
    const float* Qb = g_Qemb + (size_t)b*SEQ*DIM;
    for (int i = tid; i < 32*DIM; i += 256){
        int r = i / DIM, d = i - r*DIM;
        sQ[i] = Qb[(size_t)(i0 + r)*DIM + d];
    }
    __syncthreads();
    int ti = (tid >> 5) * 4;
    int tj = (tid & 31) * 4;
    float acc[4][4];
#pragma unroll
    for (int a = 0; a < 4; a++)
#pragma unroll
        for (int c = 0; c < 4; c++) acc[a][c] = 0.f;
    const float4* qi0 = (const float4*)(sQ + (ti+0)*DIM);
    const float4* qi1 = (const float4*)(sQ + (ti+1)*DIM);
    const float4* qi2 = (const float4*)(sQ + (ti+2)*DIM);
    const float4* qi3 = (const float4*)(sQ + (ti+3)*DIM);
    const float4* qj0 = (const float4*)(Qb + (size_t)(tj+0)*DIM);
    const float4* qj1 = (const float4*)(Qb + (size_t)(tj+1)*DIM);
    const float4* qj2 = (const float4*)(Qb + (size_t)(tj+2)*DIM);
    const float4* qj3 = (const float4*)(Qb + (size_t)(tj+3)*DIM);
#pragma unroll
    for (int k = 0; k < 25; k++){
        float4 A0 = qi0[k], A1 = qi1[k], A2 = qi2[k], A3 = qi3[k];
        float4 B0 = __ldg(qj0+k), B1 = __ldg(qj1+k), B2 = __ldg(qj2+k), B3 = __ldg(qj3+k);
        FMA4A(acc[0][0],A0,B0) FMA4A(acc[0][1],A0,B1) FMA4A(acc[0][2],A0,B2) FMA4A(acc[0][3],A0,B3)
        FMA4A(acc[1][0],A1,B0) FMA4A(acc[1][1],A1,B1) FMA4A(acc[1][2],A1,B2) FMA4A(acc[1][3],A1,B3)
        FMA4A(acc[2][0],A2,B0) FMA4A(acc[2][1],A2,B1) FMA4A(acc[2][2],A2,B2) FMA4A(acc[2][3],A2,B3)
        FMA4A(acc[3][0],A3,B0) FMA4A(acc[3][1],A3,B1) FMA4A(acc[3][2],A3,B2) FMA4A(acc[3][3],A3,B3)
    }
    float* Gb = g_G + (size_t)b*SEQ*SEQ;
#pragma unroll
    for (int a = 0; a < 4; a++)
#pragma unroll
        for (int c = 0; c < 4; c++)
            Gb[(size_t)(i0+ti+a)*SEQ + (tj+c)] = acc[a][c];
}

// ---------------- top-10 (coalesced via Gram symmetry, register-cached) ----------------
__global__ void k_topk(){
    int wg   = blockIdx.x*(blockDim.x >> 5) + (threadIdx.x >> 5);
    int lane = threadIdx.x & 31;
    if (wg >= 116*BATCH) return;
    int t = 11 + wg / BATCH;
    int b = wg % BATCH;
    // G is symmetric bit-identically (same d-sequential fma order both ways),
    // so read row t+1 contiguously instead of column t+1.
    const float* Grow = g_G + ((size_t)b*SEQ + (t+1))*SEQ;
    float val[4];
#pragma unroll
    for (int m = 0; m < 4; m++){
        int s = lane + 32*m;
        val[m] = (s < t) ? __ldg(&Grow[s]) : -INFINITY;
    }
    unsigned selm = 0;
    for (int r = 0; r < RKN; r++){
        float bv = -INFINITY; int bi = SEQ;
#pragma unroll
        for (int m = 0; m < 4; m++){
            int s = lane + 32*m;
            if (s < t && !((selm >> m) & 1u)){
                float v = val[m];
                if (v > bv || (v == bv && s < bi)){ bv = v; bi = s; }
            }
        }
#pragma unroll
        for (int o = 16; o; o >>= 1){
            float ov = __shfl_xor_sync(0xFFFFFFFFu, bv, o);
            int   oi = __shfl_xor_sync(0xFFFFFFFFu, bi, o);
            if (ov > bv || (ov == bv && oi < bi)){ bv = ov; bi = oi; }
        }
        if ((bi & 31) == lane) selm |= 1u << (bi >> 5);
        if (lane == 0) g_top[((size_t)t*BATCH + b)*RKN + r] = bi;
    }
}

// ---------------- merged aggregate + qc (R7 proven version) ----------------
__global__ void __launch_bounds__(256) k_aggqc(
    const float* __restrict__ Eq, const float* __restrict__ Ec,
    const int* __restrict__ question, const int* __restrict__ mask,
    const int* __restrict__ qnb, const int* __restrict__ snb,
    const float* __restrict__ Wagg, const float* __restrict__ bagg,
    const float* __restrict__ Wlast, const float* __restrict__ blast,
    const int* __restrict__ concept_idx, const void* __restrict__ cmask,
    const float* __restrict__ W_key, const float* __restrict__ b_key,
    const float* __restrict__ W_W)
{
    int tb = blockIdx.x;
    int t = tb >> 7, b = tb & 127;

    __shared__ __align__(16) float sE1[4*DIM], sE2[16*DIM], sU[16*DIM], sV[16*DIM];
    __shared__ __align__(16) float sV1[4*DIM], sT4[4*DIM], sW1[4*DIM];
    __shared__ __align__(16) float vA[DIM], vB[DIM], vC[DIM];
    __shared__ int sN1[4], sN2[16], sN3[64];
    __shared__ __align__(16) float sqc[5*DIM], sQt[5*DIM];

    if (threadIdx.x < 128){
        // ================= aggregation half =================
        int tid = threadIdx.x;
        int q_t = question[b*SEQ + t];
        float* dst = g_EMB + (size_t)tb*DIM;
        if (mask[b*SEQ + t] == 0){
            for (int d = tid; d < DIM; d += 128) dst[d] = __ldg(&Eq[(size_t)q_t*DIM + d]);
        } else {
            if (tid < QNB) sN1[tid] = __ldg(&qnb[q_t*QNB + tid]);
            BAR1();
            if (tid < 16) sN2[tid] = __ldg(&snb[sN1[tid >> 2]*SNB + (tid & 3)]);
            BAR1();
            if (tid < 64) sN3[tid] = __ldg(&qnb[sN2[tid >> 2]*QNB + (tid & 3)]);
            for (int i = tid; i < 4*DIM; i += 128){
                int r = i / DIM, d = i - r*DIM;
                sE1[i] = __ldg(&Ec[(size_t)sN1[r]*DIM + d]);
            }
            BAR1();
            for (int i = tid; i < 16*DIM; i += 128){
                int k = i / DIM, d = i - k*DIM;
                float e2v = __ldg(&Eq[(size_t)sN2[k]*DIM + d]);
                float s3 = __ldg(&Ec[(size_t)sN3[4*k+0]*DIM + d]) + __ldg(&Ec[(size_t)sN3[4*k+1]*DIM + d])
                         + __ldg(&Ec[(size_t)sN3[4*k+2]*DIM + d]) + __ldg(&Ec[(size_t)sN3[4*k+3]*DIM + d]);
                sE2[i] = e2v;
                sU[i]  = e2v + 0.25f*s3;
            }
            BAR1();
            // ---- stage i=0: sV[k][o] = tanh(Wagg2 @ sU[k] + b2), 4o x 4k register tiles ----
            for (int task = tid; task < 100; task += 128){
                int og = task % 25, kg = task / 25;
                int o0 = og*4, k0 = kg*4;
                float acc[4][4];
#pragma unroll
                for (int a = 0; a < 4; a++)
#pragma unroll
                    for (int c = 0; c < 4; c++) acc[a][c] = 0.f;
                const float4* w0 = (const float4*)(Wagg + 2*DIM*DIM + (o0+0)*DIM);
                const float4* w1 = (const float4*)(Wagg + 2*DIM*DIM + (o0+1)*DIM);
                const float4* w2 = (const float4*)(Wagg + 2*DIM*DIM + (o0+2)*DIM);
                const float4* w3 = (const float4*)(Wagg + 2*DIM*DIM + (o0+3)*DIM);
                const float4* x0 = (const float4*)(sU + (k0+0)*DIM);
                const float4* x1 = (const float4*)(sU + (k0+1)*DIM);
                const float4* x2 = (const float4*)(sU + (k0+2)*DIM);
                const float4* x3 = (const float4*)(sU + (k0+3)*DIM);
#pragma unroll
                for (int i = 0; i < 25; i++){
                    float4 W0 = __ldg(w0+i), W1 = __ldg(w1+i), W2 = __ldg(w2+i), W3 = __ldg(w3+i);
                    float4 X0 = x0[i], X1 = x1[i], X2 = x2[i], X3 = x3[i];
                    FMA4A(acc[0][0],W0,X0) FMA4A(acc[0][1],W0,X1) FMA4A(acc[0][2],W0,X2) FMA4A(acc[0][3],W0,X3)
                    FMA4A(acc[1][0],W1,X0) FMA4A(acc[1][1],W1,X1) FMA4A(acc[1][2],W1,X2) FMA4A(acc[1][3],W1,X3)
                    FMA4A(acc[2][0],W2,X0) FMA4A(acc[2][1],W2,X1) FMA4A(acc[2][2],W2,X2) FMA4A(acc[2][3],W2,X3)
                    FMA4A(acc[3][0],W3,X0) FMA4A(acc[3][1],W3,X1) FMA4A(acc[3][2],W3,X2) FMA4A(acc[3][3],W3,X3)
                }
#pragma unroll
                for (int a = 0; a < 4; a++){
                    float bb = __ldg(&bagg[2*DIM + o0 + a]);
#pragma unroll
                    for (int c = 0; c < 4; c++)
                        sV[(k0+c)*DIM + (o0+a)] = tanhf(acc[a][c] + bb);
                }
            }
            for (int i = tid; i < 4*DIM; i += 128){
                int r = i / DIM, d = i - r*DIM;
                sT4[i] = sE1[i] + 0.25f*(sE2[(4*r+0)*DIM+d] + sE2[(4*r+1)*DIM+d]
                                       + sE2[(4*r+2)*DIM+d] + sE2[(4*r+3)*DIM+d]);
            }
            for (int d = tid; d < DIM; d += 128)
                vA[d] = __ldg(&Eq[(size_t)q_t*DIM + d]) + 0.25f*(sE1[d] + sE1[DIM+d] + sE1[2*DIM+d] + sE1[3*DIM+d]);
            BAR1();
            // ---- sV1 = tanh(Wagg1 @ sT4) (2o x 4r), vB = tanh(Wagg0 @ vA) (2o) ----
            for (int task = tid; task < 100; task += 128){
                if (task < 50){
                    int o0 = task*2;
                    float acc[2][4];
#pragma unroll
                    for (int a = 0; a < 2; a++)
#pragma unroll
                        for (int c = 0; c < 4; c++) acc[a][c] = 0.f;
                    const float4* w0 = (const float4*)(Wagg + DIM*DIM + (o0+0)*DIM);
                    const float4* w1 = (const float4*)(Wagg + DIM*DIM + (o0+1)*DIM);
                    const float4* x0 = (const float4*)(sT4 + 0*DIM);
                    const float4* x1 = (const float4*)(sT4 + 1*DIM);
                    const float4* x2 = (const float4*)(sT4 + 2*DIM);
                    const float4* x3 = (const float4*)(sT4 + 3*DIM);
#pragma unroll
                    for (int i = 0; i < 25; i++){
                        float4 W0 = __ldg(w0+i), W1 = __ldg(w1+i);
                        float4 X0 = x0[i], X1 = x1[i], X2 = x2[i], X3 = x3[i];
                        FMA4A(acc[0][0],W0,X0) FMA4A(acc[0][1],W0,X1) FMA4A(acc[0][2],W0,X2) FMA4A(acc[0][3],W0,X3)
                        FMA4A(acc[1][0],W1,X0) FMA4A(acc[1][1],W1,X1) FMA4A(acc[1][2],W1,X2) FMA4A(acc[1][3],W1,X3)
                    }
#pragma unroll
                    for (int a = 0; a < 2; a++){
                        float bb = __ldg(&bagg[DIM + o0 + a]);
#pragma unroll
                        for (int c = 0; c < 4; c++)
                            sV1[c*DIM + (o0+a)] = tanhf(acc[a][c] + bb);
                    }
                } else {
                    int o0 = (task - 50)*2;
                    float a0 = dotw<25>(Wagg + (o0+0)*DIM, vA);
                    float a1 = dotw<25>(Wagg + (o0+1)*DIM, vA);
                    vB[o0+0] = tanhf(a0 + __ldg(&bagg[o0+0]));
                    vB[o0+1] = tanhf(a1 + __ldg(&bagg[o0+1]));
                }
            }
            BAR1();
            // ---- stage i=1 averaging ----
            for (int i = tid; i < 4*DIM; i += 128){
                int r = i / DIM, d = i - r*DIM;
                sT4[i] = sV1[i] + 0.25f*(sV[(4*r+0)*DIM+d] + sV[(4*r+1)*DIM+d]
                                       + sV[(4*r+2)*DIM+d] + sV[(4*r+3)*DIM+d]);
            }
            for (int d = tid; d < DIM; d += 128)
                vA[d] = vB[d] + 0.25f*(sV1[d] + sV1[DIM+d] + sV1[2*DIM+d] + sV1[3*DIM+d]);
            BAR1();
            // ---- sW1 = tanh(Wagg1 @ sT4) (2o x 4r), vC = tanh(Wagg0 @ vA) (2o) ----
            for (int task = tid; task < 100; task += 128){
                if (task < 50){
                    int o0 = task*2;
                    float acc[2][4];
#pragma unroll
                    for (int a = 0; a < 2; a++)
#pragma unroll
                        for (int c = 0; c < 4; c++) acc[a][c] = 0.f;
                    const float4* w0 = (const float4*)(Wagg + DIM*DIM + (o0+0)*DIM);
                    const float4* w1 = (const float4*)(Wagg + DIM*DIM + (o0+1)*DIM);
                    const float4* x0 = (const float4*)(sT4 + 0*DIM);
                    const float4* x1 = (const float4*)(sT4 + 1*DIM);
                    const float4* x2 = (const float4*)(sT4 + 2*DIM);
                    const float4* x3 = (const float4*)(sT4 + 3*DIM);
#pragma unroll
                    for (int i = 0; i < 25; i++){
                        float4 W0 = __ldg(w0+i), W1 = __ldg(w1+i);
                        float4 X0 = x0[i], X1 = x1[i], X2 = x2[i], X3 = x3[i];
                        FMA4A(acc[0][0],W0,X0) FMA4A(acc[0][1],W0,X1) FMA4A(acc[0][2],W0,X2) FMA4A(acc[0][3],W0,X3)
                        FMA4A(acc[1][0],W1,X0) FMA4A(acc[1][1],W1,X1) FMA4A(acc[1][2],W1,X2) FMA4A(acc[1][3],W1,X3)
                    }
#pragma unroll
                    for (int a = 0; a < 2; a++){
                        float bb = __ldg(&bagg[DIM + o0 + a]);
#pragma unroll
                        for (int c = 0; c < 4; c++)
                            sW1[c*DIM + (o0+a)] = tanhf(acc[a][c] + bb);
                    }
                } else {
                    int o0 = (task - 50)*2;
                    float a0 = dotw<25>(Wagg + (o0+0)*DIM, vA);
                    float a1 = dotw<25>(Wagg + (o0+1)*DIM, vA);
                    vC[o0+0] = tanhf(a0 + __ldg(&bagg[o0+0]));
                    vC[o0+1] = tanhf(a1 + __ldg(&bagg[o0+1]));
                }
            }
            BAR1();
            // ---- stage i=2 ----
            for (int d = tid; d < DIM; d += 128)
                vA[d] = vC[d] + 0.25f*(sW1[d] + sW1[DIM+d] + sW1[2*DIM+d] + sW1[3*DIM+d]);
            BAR1();
            for (int task = tid; task < 50; task += 128){
                int o0 = task*2;
                float a0 = dotw<25>(Wagg + (o0+0)*DIM, vA);
                float a1 = dotw<25>(Wagg + (o0+1)*DIM, vA);
                vB[o0+0] = tanhf(a0 + __ldg(&bagg[o0+0]));
                vB[o0+1] = tanhf(a1 + __ldg(&bagg[o0+1]));
            }
            BAR1();
            for (int task = tid; task < 50; task += 128){
                int o0 = task*2;
                float a0 = dotw<25>(Wlast + (o0+0)*DIM, vB);
                float a1 = dotw<25>(Wlast + (o0+1)*DIM, vB);
                dst[o0+0] = tanhf(a0 + __ldg(&blast[o0+0]));
                dst[o0+1] = tanhf(a1 + __ldg(&blast[o0+1]));
            }
        }
    } else {
        // ================= qc half =================
        int tid = threadIdx.x - 128;
        int qn = question[b*SEQ + t + 1];
        int mode = g_cm_mode;
        for (int i = tid; i < 5*DIM; i += 128){
            int q = i / DIM, d = i - q*DIM;
            float v;
            if (q == 0){
                v = g_Qemb[((size_t)b*SEQ + t + 1)*DIM + d];
            } else {
                int fi = qn*KCN + (q - 1);
                bool mk;
                if (mode == 1)      mk = ((const int*)cmask)[fi] != 0;
                else if (mode == 2) mk = ((const float*)cmask)[fi] != 0.f;
                else                mk = ((const unsigned char*)cmask)[fi] != 0;
                int ci = __ldg(&concept_idx[fi]);
                v = mk ? __ldg(&Ec[(size_t)ci*DIM + d]) : 0.f;
            }
            sqc[i] = v;
            g_qc[((size_t)tb)*(5*DIM) + i] = v;
        }
        BAR2();
        for (int task = tid; task < 50; task += 128){
            int o0 = task*2;
            float acc[2][5];
#pragma unroll
            for (int a = 0; a < 2; a++)
#pragma unroll
                for (int c = 0; c < 5; c++) acc[a][c] = 0.f;
            const float4* w0 = (const float4*)(W_key + (o0+0)*DIM);
            const float4* w1 = (const float4*)(W_key + (o0+1)*DIM);
            const float4* x0 = (const float4*)(sqc + 0*DIM);
            const float4* x1 = (const float4*)(sqc + 1*DIM);
            const float4* x2 = (const float4*)(sqc + 2*DIM);
            const float4* x3 = (const float4*)(sqc + 3*DIM);
            const float4* x4 = (const float4*)(sqc + 4*DIM);
#pragma unroll
            for (int i = 0; i < 25; i++){
                float4 W0 = __ldg(w0+i), W1 = __ldg(w1+i);
                float4 X0 = x0[i], X1 = x1[i], X2 = x2[i], X3 = x3[i], X4 = x4[i];
                FMA4A(acc[0][0],W0,X0) FMA4A(acc[0][1],W0,X1) FMA4A(acc[0][2],W0,X2) FMA4A(acc[0][3],W0,X3) FMA4A(acc[0][4],W0,X4)
                FMA4A(acc[1][0],W1,X0) FMA4A(acc[1][1],W1,X1) FMA4A(acc[1][2],W1,X2) FMA4A(acc[1][3],W1,X3) FMA4A(acc[1][4],W1,X4)
            }
#pragma unroll
            for (int a = 0; a < 2; a++){
                float bb = __ldg(&b_key[o0+a]);
#pragma unroll
                for (int c = 0; c < 5; c++)
                    sQt[c*DIM + (o0+a)] = tanhf(acc[a][c] + bb);
            }
        }
        BAR2();
        int w = tid >> 5, lane = tid & 31;
        for (int q = w; q < 5; q += 4){
            float part = 0.f;
            for (int d = lane; d < DIM; d += 32) part += sQt[q*DIM + d] * __ldg(&W_W[d]);
            part = wredsum(part);
            if (lane == 0) g_qtw[((size_t)tb)*5 + q] = part;
        }
    }
}

// ---------------- gi1 ----------------
__global__ void __launch_bounds__(256) k_gi1(const float* __restrict__ Wih1,
                                             const int* __restrict__ response){
    int t = blockIdx.x, zb = blockIdx.y;
    int tid = threadIdx.x;
    __shared__ __align__(16) float sE[DIM*64];
    __shared__ int sRt[64];
    for (int i = tid; i < 64*DIM; i += 256){
        int bb = i / DIM, d = i - bb*DIM;
        sE[d*64 + bb] = g_EMB[((size_t)t*BATCH + zb*64 + bb)*DIM + d];
    }
    if (tid < 64) sRt[tid] = response[(zb*64 + tid)*SEQ + t];
    __syncthreads();
    for (int tt = tid; tt < 600; tt += 256){
        int ro = (tt >> 3) * 4;
        int bo = (tt & 7) * 8;
        float acc[4][8];
#pragma unroll
        for (int i = 0; i < 4; i++)
#pragma unroll
            for (int j = 0; j < 8; j++) acc[i][j] = 0.f;
        for (int k = 0; k < DIM; k++){
            float w0 = __ldg(&Wih1[(size_t)(ro+0)*2*DIM + k]);
            float w1 = __ldg(&Wih1[(size_t)(ro+1)*2*DIM + k]);
            float w2 = __ldg(&Wih1[(size_t)(ro+2)*2*DIM + k]);
            float w3 = __ldg(&Wih1[(size_t)(ro+3)*2*DIM + k]);
            const float* e = sE + k*64 + bo;
#pragma unroll
            for (int j = 0; j < 8; j++){
                float ev = e[j];
                acc[0][j] = fmaf(w0, ev, acc[0][j]);
                acc[1][j] = fmaf(w1, ev, acc[1][j]);
                acc[2][j] = fmaf(w2, ev, acc[2][j]);
                acc[3][j] = fmaf(w3, ev, acc[3][j]);
            }
        }
#pragma unroll
        for (int i = 0; i < 4; i++)
#pragma unroll
            for (int j = 0; j < 8; j++){
                int b = zb*64 + bo + j;
                int o = ro + i;
                g_GI1[((size_t)t*BATCH + b)*300 + o] = acc[i][j] + g_gier[sRt[bo+j]*300 + o];
            }
    }
}

// ---------------- pipelined scan (R7 proven 2-row version) ----------------
__global__ void __launch_bounds__(320) k_scan2(
    const float* __restrict__ Whh1, const float* __restrict__ bhh1,
    const float* __restrict__ Wih2, const float* __restrict__ bih2,
    const float* __restrict__ Whh2, const float* __restrict__ bhh2,
    const float* __restrict__ h1i, const float* __restrict__ h2i)
{
    extern __shared__ __align__(16) float sW[];
    __shared__ __align__(16) float sH[2][DIM], sX[2][DIM];
    __shared__ __align__(16) float sGa[2][300], sGb[2][300];
    __shared__ float sba[300], sbb[300];

    int tid = threadIdx.x;
    int role = blockIdx.x >> 6;
    int pair = blockIdx.x & 63;
    int b0 = pair*2;

    if (role == 0){
        for (int i = tid; i < 30000; i += 320) sW[i] = Whh1[i];
        for (int i = tid; i < 300; i += 320) sba[i] = bhh1[i];
        for (int i = tid; i < DIM; i += 320){
            sH[0][i] = h1i[b0*DIM+i]; sH[1][i] = h1i[(b0+1)*DIM+i];
        }
        __syncthreads();
        for (int t = 0; t < TSTEPS; t++){
            if (tid < 300){
                float a0 = sba[tid], a1 = sba[tid];
                dot2s(sW + tid*DIM, sH[0], sH[1], a0, a1);
                sGa[0][tid] = a0; sGa[1][tid] = a1;
            }
            for (int i = tid; i < 600; i += 320){
                int r = i / 300, o = i - r*300;
                sGb[r][o] = g_GI1[((size_t)t*BATCH + b0 + r)*300 + o];
            }
            __syncthreads();
            for (int i = tid; i < 200; i += 320){
                int r = i / 100, d = i - r*100;
                float rr = sigm(sGb[r][d]       + sGa[r][d]);
                float zz = sigm(sGb[r][DIM+d]   + sGa[r][DIM+d]);
                float nn = tanhf(sGb[r][2*DIM+d] + rr*sGa[r][2*DIM+d]);
                float h1n = (1.f - zz)*nn + zz*sH[r][d];
                sH[r][d] = h1n;
                g_H1N[((size_t)t*BATCH + b0 + r)*DIM + d] = h1n;
            }
            __syncthreads();
            if (tid == 0){
                __threadfence();
                atomicExch(&g_SYNC[pair], t + 1);
            }
        }
    } else {
        for (int i = tid; i < 30000; i += 320) sW[i] = Wih2[i];
        for (int i = tid; i < 300; i += 320){ sba[i] = bhh2[i]; sbb[i] = bih2[i]; }
        for (int i = tid; i < DIM; i += 320){
            sH[0][i] = h2i[b0*DIM+i]; sH[1][i] = h2i[(b0+1)*DIM+i];
        }
        __syncthreads();
        for (int t = 0; t < TSTEPS; t++){
            if (tid < 300){
                float a0 = sba[tid], a1 = sba[tid];
                dot2g(Whh2 + tid*DIM, sH[0], sH[1], a0, a1);
                sGa[0][tid] = a0; sGa[1][tid] = a1;
            }
            if (tid == 0){
                while (atomicAdd(&g_SYNC[pair], 0) < t + 1) __nanosleep(60);
                __threadfence();
            }
            __syncthreads();
            for (int i = tid; i < 200; i += 320){
                int r = i / 100, d = i - r*100;
                sX[r][d] = g_H1N[((size_t)t*BATCH + b0 + r)*DIM + d];
            }
            __syncthreads();
            if (tid < 300){
                float a0 = sbb[tid], a1 = sbb[tid];
                dot2s(sW + tid*DIM, sX[0], sX[1], a0, a1);
                sGb[0][tid] = a0; sGb[1][tid] = a1;
            }
            __syncthreads();
            for (int i = tid; i < 200; i += 320){
                int r = i / 100, d = i - r*100;
                float rr = sigm(sGb[r][d]       + sGa[r][d]);
                float zz = sigm(sGb[r][DIM+d]   + sGa[r][DIM+d]);
                float nn = tanhf(sGb[r][2*DIM+d] + rr*sGa[r][2*DIM+d]);
                float g2 = (1.f - zz)*nn + zz*sH[r][d];
                g_G2ALL[((size_t)t*BATCH + b0 + r)*DIM + d] = g2;
                if (t > 0) sH[r][d] = g2;
            }
            __syncthreads();
        }
    }
}

// ---------------- ktw, 4 per block ----------------
__global__ void __launch_bounds__(128) k_ktw(const float* __restrict__ Wquery,
                                             const float* __restrict__ bquery,
                                             const float* __restrict__ WW){
    int tb0 = blockIdx.x*4;
    int tid = threadIdx.x;
    __shared__ __align__(16) float sg2[4][DIM];
    __shared__ float sred[4][DIM];
    for (int i = tid; i < 4*DIM; i += 128){
        int j = i / DIM, d = i - j*DIM;
        sg2[j][d] = g_G2ALL[(size_t)(tb0 + j)*DIM + d];
    }
    __syncthreads();
    for (int o = tid; o < DIM; o += 128){
        float a0=0.f,a1=0.f,a2=0.f,a3=0.f;
        dot4(Wquery + o*DIM, sg2[0], sg2[1], sg2[2], sg2[3], a0,a1,a2,a3);
        float bq = __ldg(&bquery[o]);
        float wk = __ldg(&WW[DIM+o]);
        sred[0][o] = tanhf(a0+bq)*wk;
        sred[1][o] = tanhf(a1+bq)*wk;
        sred[2][o] = tanhf(a2+bq)*wk;
        sred[3][o] = tanhf(a3+bq)*wk;
    }
    __syncthreads();
    int w = tid >> 5, lane = tid & 31;
    float v = sred[w][lane] + sred[w][lane+32] + sred[w][lane+64]
            + (lane < 4 ? sred[w][lane+96] : 0.f);
    v = wredsum(v);
    if (lane == 0) g_KTW[tb0 + w] = v;
}

// ---------------- predict ----------------
__global__ void __launch_bounds__(128) k_predict(const float* __restrict__ bW,
                                                 float* __restrict__ out){
    int tb = blockIdx.x;
    int t = tb >> 7, b = tb & 127;
    int tid = threadIdx.x;
    __shared__ __align__(16) float sSt[11*DIM];
    __shared__ float sOg[55], sKtw[11], sQtw[5], sP[5];
    __shared__ int sSrc[11];

    if (tid < 11){
        int src = 0;
        float k;
        if (tid == 0){
            k = g_KTW[tb];
        } else {
            src = (t > RKN) ? g_top[((size_t)t*BATCH + b)*RKN + (tid-1)] : (tid-1);
            k = (src == 0) ? g_kz : g_KTW[(size_t)src*BATCH + b];
        }
        sSrc[tid] = src;
        sKtw[tid] = k;
    }
    if (tid >= 11 && tid < 16) sQtw[tid-11] = g_qtw[(size_t)tb*5 + (tid-11)];
    __syncthreads();
    for (int i = tid; i < 11*DIM; i += 128){
        int s = i / DIM, d = i - s*DIM;
        float v;
        if (s == 0) v = g_G2ALL[(size_t)tb*DIM + d];
        else {
            int src = sSrc[s];
            v = (src == 0) ? 0.f : g_G2ALL[((size_t)src*BATCH + b)*DIM + d];
        }
        sSt[i] = v;
    }
    __syncthreads();
    if (tid < 55){
        int q = tid / 11, s = tid - q*11;
        const float4* a = (const float4*)(g_qc + (size_t)tb*(5*DIM) + q*DIM);
        const float4* xx = (const float4*)(sSt + s*DIM);
        float acc = 0.f;
#pragma unroll
        for (int i = 0; i < 25; i++){
            float4 w = __ldg(a+i), u = xx[i];
            acc = fmaf(w.x,u.x,acc); acc = fmaf(w.y,u.y,acc);
            acc = fmaf(w.z,u.z,acc); acc = fmaf(w.w,u.w,acc);
        }
        sOg[tid] = acc;
    }
    __syncthreads();
    if (tid < 5){
        int q = tid;
        float bw0 = __ldg(&bW[0]);
        float qt = sQtw[q];
        float tmp[11]; float mx = -INFINITY;
#pragma unroll
        for (int s = 0; s < 11; s++){
            bool valid = (s == 0) || (t > RKN) || ((s-1) < t);
            float v = valid ? (qt + sKtw[s] + bw0) : NEGV;
            tmp[s] = v; mx = fmaxf(mx, v);
        }
        float se = 0.f, acc = 0.f;
#pragma unroll
        for (int s = 0; s < 11; s++){
            float e = expf(tmp[s] - mx);
            se += e; acc += e * sOg[q*11 + s];
        }
        sP[q] = acc / se;
    }
    __syncthreads();
    if (tid == 0){
        float p = sP[0] + sP[1] + sP[2] + sP[3] + sP[4];
        int col = (t == 0) ? 0 : (t + 1);
        out[b*SEQ + col] = p;
    }
}

// ---------------- launch ----------------
extern "C" void kernel_launch(void* const* d_in, const int* in_sizes, int n_in,
                              void* d_out, int out_size){
    const float* Eq     = (const float*)d_in[0];
    const float* Ec     = (const float*)d_in[1];
    const float* Er     = (const float*)d_in[2];
    const float* Wih1   = (const float*)d_in[3];
    const float* Whh1   = (const float*)d_in[4];
    const float* bih1   = (const float*)d_in[5];
    const float* bhh1   = (const float*)d_in[6];
    const float* Wih2   = (const float*)d_in[7];
    const float* Whh2   = (const float*)d_in[8];
    const float* bih2   = (const float*)d_in[9];
    const float* bhh2   = (const float*)d_in[10];
    const float* Wagg   = (const float*)d_in[11];
    const float* bagg   = (const float*)d_in[12];
    const float* Wlast  = (const float*)d_in[13];
    const float* blast  = (const float*)d_in[14];
    const float* Wquery = (const float*)d_in[15];
    const float* bquery = (const float*)d_in[16];
    const float* Wkey   = (const float*)d_in[17];
    const float* bkey   = (const float*)d_in[18];
    const float* WW     = (const float*)d_in[19];
    const float* bW     = (const float*)d_in[20];
    const float* h1i    = (const float*)d_in[21];
    const float* h2i    = (const float*)d_in[22];
    const int* question = (const int*)d_in[23];
    const int* response = (const int*)d_in[24];
    const int* maskp    = (const int*)d_in[25];
    const int* qnb      = (const int*)d_in[26];
    const int* snb      = (const int*)d_in[27];
    const int* cidx     = (const int*)d_in[28];
    const void* cmask   = d_in[29];
    float* out = (float*)d_out;

    cudaFuncSetAttribute(k_scan2, cudaFuncAttributeMaxDynamicSharedMemorySize, 122880);

    k_pre<<<2048, 256>>>(Eq, question, (const unsigned char*)cmask, bquery, WW,
                         Wih1, bih1, Er, out);
    k_gmat<<<dim3(4, BATCH), 256>>>();
    {
        int nwarp = 116*BATCH;
        int nb = (nwarp + 7) / 8;
        k_topk<<<nb, 256>>>();
    }
    k_aggqc<<<TSTEPS*BATCH, 256>>>(Eq, Ec, question, maskp, qnb, snb,
                                   Wagg, bagg, Wlast, blast,
                                   cidx, cmask, Wkey, bkey, WW);
    k_gi1<<<dim3(TSTEPS, 2), 256>>>(Wih1, response);
    k_scan2<<<128, 320, 120000>>>(Whh1, bhh1, Wih2, bih2, Whh2, bhh2, h1i, h2i);
    k_ktw<<<TSTEPS*BATCH/4, 128>>>(Wquery, bquery, WW);
    k_predict<<<TSTEPS*BATCH, 128>>>(bW, out);
}